// round 1
// baseline (speedup 1.0000x reference)
#include <cuda_runtime.h>
#include <math.h>

#define BATCHES 8
#define NMAX    128
#define PE      64
#define NE      5
#define DS      64
#define NF      8
#define TOTAL   (BATCHES*NMAX)       // 1024
#define PROJC   (4*NE*PE)            // 1280
#define ZCOUNT  (BATCHES*NE*NMAX*NMAX)

#define OFF_EHAT 0
#define OFF_XHAT (BATCHES*NMAX*NMAX*NE)            // 655360
#define OFF_EDGE (OFF_XHAT + TOTAL*NF)             // 663552
#define OFF_MASK (OFF_EDGE + BATCHES*NMAX*NMAX)    // 794624

__device__ float g_proj[TOTAL*PROJC];
__device__ float g_z[ZCOUNT];
__device__ float g_a[BATCHES*NE*NMAX];
__device__ float g_r[BATCHES*NMAX];
__device__ int   g_node[BATCHES*NMAX];
__device__ int   g_mask[BATCHES*NMAX];
__device__ int   g_cnt[BATCHES];
__device__ float g_coef[BATCHES];
__device__ float g_u[DS];
__device__ float g_v[DS];

// ---------------------------------------------------------------------------
// K0: dense mapping (batch is sorted), per-graph counts, coef, u/v vectors,
// and the float mask output region.
// ---------------------------------------------------------------------------
__global__ void k_setup(const int* __restrict__ batch, const float* __restrict__ q,
                        const float* __restrict__ w_phi, const float* __restrict__ b_phi,
                        const float* __restrict__ w_ctx, float* __restrict__ out_mask) {
    __shared__ int s_start[BATCHES];
    __shared__ int s_cnt[BATCHES];
    int t = threadIdx.x;                // 0..1023, one block
    if (t < BATCHES) { s_cnt[t] = 0; s_start[t] = 0; }
    g_node[t] = -1;
    g_mask[t] = 0;
    out_mask[t] = 0.0f;
    __syncthreads();
    int b = batch[t];
    if (t == 0 || batch[t-1] != b) s_start[b] = t;
    atomicAdd(&s_cnt[b], 1);
    __syncthreads();
    int pos = t - s_start[b];
    int di = b*NMAX + pos;
    g_node[di] = t;
    g_mask[di] = 1;
    out_mask[di] = 1.0f;
    if (t < BATCHES) {
        g_cnt[t] = s_cnt[t];
        float qq = q[t];
        float c = cosf(6.283185307179586f*qq);
        float s = sinf(6.283185307179586f*qq);
        g_coef[t] = (2.0f - c) / s;
    }
    if (t < DS) {
        float u = 0.f, v = 0.f;
        #pragma unroll 8
        for (int k = 0; k < DS; k++) {
            float wc = w_ctx[k*DS + t];
            u = fmaf(w_phi[k], wc, u);
            v = fmaf(b_phi[k], wc, v);
        }
        g_u[t] = u; g_v[t] = v;
    }
}

// ---------------------------------------------------------------------------
// K1: proj = x @ w_attn + b_attn, written directly in dense layout
// (zeros at invalid dense slots). M=1024, N=1280, K=64. Tile 64x64.
// ---------------------------------------------------------------------------
__global__ void k_proj(const float* __restrict__ x, const float* __restrict__ w,
                       const float* __restrict__ bias) {
    __shared__ float As[64][65];
    __shared__ float Ws[64][65];
    int tid = threadIdx.x;              // 256 threads
    int tx = tid & 15, ty = tid >> 4;   // 16x16
    int row0 = blockIdx.y * 64;
    int col0 = blockIdx.x * 64;
    #pragma unroll
    for (int l = 0; l < 16; l++) {
        int e = tid + l*256;
        int r = e >> 6, k = e & 63;
        int node = g_node[row0 + r];
        As[r][k] = (node >= 0) ? x[node*PE + k] : 0.0f;
    }
    #pragma unroll
    for (int l = 0; l < 16; l++) {
        int e = tid + l*256;
        int k = e >> 6, c = e & 63;
        Ws[k][c] = w[k*PROJC + col0 + c];
    }
    __syncthreads();
    float acc[4][4] = {};
    #pragma unroll 8
    for (int k = 0; k < 64; k++) {
        float a[4], bv[4];
        #pragma unroll
        for (int i = 0; i < 4; i++) a[i] = As[ty + i*16][k];
        #pragma unroll
        for (int j = 0; j < 4; j++) bv[j] = Ws[k][tx + j*16];
        #pragma unroll
        for (int i = 0; i < 4; i++)
            #pragma unroll
            for (int j = 0; j < 4; j++)
                acc[i][j] = fmaf(a[i], bv[j], acc[i][j]);
    }
    #pragma unroll
    for (int i = 0; i < 4; i++) {
        int r = row0 + ty + i*16;
        int node = g_node[r];
        #pragma unroll
        for (int j = 0; j < 4; j++) {
            int c = col0 + tx + j*16;
            g_proj[r*PROJC + c] = (node >= 0) ? (acc[i][j] + bias[c]) : 0.0f;
        }
    }
}

// ---------------------------------------------------------------------------
// K1b: x_hat = x @ w_node + b_node (original node order).
// ---------------------------------------------------------------------------
__global__ void k_xhat(const float* __restrict__ x, const float* __restrict__ w,
                       const float* __restrict__ bias, float* __restrict__ out_xhat) {
    int id = blockIdx.x*blockDim.x + threadIdx.x;   // 8192
    int node = id / NF, f = id % NF;
    float acc = 0.f;
    #pragma unroll 8
    for (int k = 0; k < PE; k++)
        acc = fmaf(__ldg(&x[node*PE + k]), __ldg(&w[k*NF + f]), acc);
    out_xhat[id] = acc + bias[f];
}

// ---------------------------------------------------------------------------
// K2: z[b,e,n,m] = scale*(k1_n . q1_m) + coef_b*scale*(k2_n . q2_m)
// grid (tile=4, e, b); block 256; each block: 32 rows x 128 cols, K=64 x2.
// ---------------------------------------------------------------------------
__global__ void k_z() {
    __shared__ float Ks[32][65];
    __shared__ float Qs[128][65];
    const float scale = 0.05590169943749474f;  // 1/sqrt(320)
    int tid = threadIdx.x;
    int tx = tid & 31, ty = tid >> 5;           // 32 x 8
    int tile = blockIdx.x, e = blockIdx.y, b = blockIdx.z;
    int row0 = tile * 32;
    int base_row = b*NMAX;
    float acc1[4][4] = {};
    float acc2[4][4] = {};
    #pragma unroll
    for (int phase = 0; phase < 2; phase++) {
        int koff = (phase == 0 ? 0 : 2*NE*PE) + e*PE;        // k1 / k2
        int qoff = (phase == 0 ? NE*PE : 3*NE*PE) + e*PE;    // q1 / q2
        if (phase) __syncthreads();
        #pragma unroll
        for (int l = 0; l < 8; l++) {
            int el = tid + l*256;
            int r = el >> 6, k = el & 63;
            Ks[r][k] = g_proj[(base_row + row0 + r)*PROJC + koff + k];
        }
        #pragma unroll
        for (int l = 0; l < 32; l++) {
            int el = tid + l*256;
            int r = el >> 6, k = el & 63;
            Qs[r][k] = g_proj[(base_row + r)*PROJC + qoff + k];
        }
        __syncthreads();
        #pragma unroll 8
        for (int k = 0; k < 64; k++) {
            float a[4], bv[4];
            #pragma unroll
            for (int i = 0; i < 4; i++) a[i] = Ks[ty + i*8][k];
            #pragma unroll
            for (int j = 0; j < 4; j++) bv[j] = Qs[tx + j*32][k];
            if (phase == 0) {
                #pragma unroll
                for (int i = 0; i < 4; i++)
                    #pragma unroll
                    for (int j = 0; j < 4; j++)
                        acc1[i][j] = fmaf(a[i], bv[j], acc1[i][j]);
            } else {
                #pragma unroll
                for (int i = 0; i < 4; i++)
                    #pragma unroll
                    for (int j = 0; j < 4; j++)
                        acc2[i][j] = fmaf(a[i], bv[j], acc2[i][j]);
            }
        }
    }
    float coef = g_coef[b];
    #pragma unroll
    for (int i = 0; i < 4; i++) {
        int n = row0 + ty + i*8;
        long zbase = (long)((b*NE + e)*NMAX + n)*NMAX;
        #pragma unroll
        for (int j = 0; j < 4; j++) {
            int m = tx + j*32;
            g_z[zbase + m] = scale * fmaf(coef, acc2[i][j], acc1[i][j]);
        }
    }
}

// ---------------------------------------------------------------------------
// K2b: per-(b,e,n) masked row sum -> a = S/denom, and r = cnt/denom.
// One warp per row.
// ---------------------------------------------------------------------------
__global__ void k_rows() {
    int w = blockIdx.x*8 + (threadIdx.x >> 5);   // 0..5119
    int lane = threadIdx.x & 31;
    int n = w % NMAX;
    int be = w / NMAX;
    int b = be / NE;
    const float* zrow = g_z + (long)w*NMAX;
    float s = 0.f;
    #pragma unroll
    for (int m = lane; m < NMAX; m += 32)
        s += zrow[m] * (float)g_mask[b*NMAX + m];
    #pragma unroll
    for (int off = 16; off > 0; off >>= 1)
        s += __shfl_xor_sync(0xffffffffu, s, off);
    if (lane == 0) {
        int mn = g_mask[b*NMAX + n];
        if (mn) {
            float sum = s - zrow[n];
            int cnt = g_cnt[b] - 1;
            float denom = fmaxf((float)cnt, 1.0f);
            g_a[w] = sum / denom;
            g_r[b*NMAX + n] = (float)cnt / denom;
        } else {
            g_a[w] = 0.0f;
            g_r[b*NMAX + n] = 0.0f;
        }
    }
}

// ---------------------------------------------------------------------------
// K3: the heavy kernel. One block per (b,e,n), 128 threads (one per m):
// e[b,e,n,m] = sum_d w_out[d]*gelu(z*ws[d] + b_self[d] + a*u[d] + r*v[d]) + b_out
// written transposed into e_hat[b,m,n,e].
// ---------------------------------------------------------------------------
__global__ void k_main(const float* __restrict__ w_self, const float* __restrict__ b_self,
                       const float* __restrict__ w_out, const float* __restrict__ b_out,
                       float* __restrict__ out_e) {
    int blk = blockIdx.x;               // (b*NE+e)*NMAX + n
    int n = blk % NMAX;
    int be = blk / NMAX;
    int e = be % NE;
    int b = be / NE;
    __shared__ float s_base[DS], s_ws[DS], s_wo[DS];
    int t = threadIdx.x;
    if (t < DS) {
        float a = g_a[blk];
        float r = g_r[b*NMAX + n];
        s_base[t] = b_self[t] + a*g_u[t] + r*g_v[t];
        s_ws[t]   = w_self[t];
        s_wo[t]   = w_out[t];
    }
    __syncthreads();
    float zv = g_z[(long)blk*NMAX + t];
    float acc = 0.f;
    #pragma unroll 8
    for (int d = 0; d < DS; d++) {
        float xx = fmaf(zv, s_ws[d], s_base[d]);
        float g = 0.5f * xx * (1.0f + erff(xx * 0.7071067811865476f));
        acc = fmaf(s_wo[d], g, acc);
    }
    out_e[((long)(b*NMAX + t)*NMAX + n)*NE + e] = acc + b_out[0];
}

// ---------------------------------------------------------------------------
// K4: edge_mask output (float 0/1).
// ---------------------------------------------------------------------------
__global__ void k_edge(float* __restrict__ out_edge) {
    int id = blockIdx.x*blockDim.x + threadIdx.x;   // 131072
    int b = id / (NMAX*NMAX);
    int rem = id - b*NMAX*NMAX;
    int n = rem >> 7, m = rem & 127;
    int v = g_mask[b*NMAX + n] & g_mask[b*NMAX + m] & (int)(n != m);
    out_edge[id] = (float)v;
}

extern "C" void kernel_launch(void* const* d_in, const int* in_sizes, int n_in,
                              void* d_out, int out_size) {
    const float* x      = (const float*)d_in[0];
    const int*   batch  = (const int*)  d_in[1];
    const float* q      = (const float*)d_in[2];
    const float* w_attn = (const float*)d_in[3];
    const float* b_attn = (const float*)d_in[4];
    const float* w_node = (const float*)d_in[5];
    const float* b_node = (const float*)d_in[6];
    const float* w_phi  = (const float*)d_in[7];
    const float* b_phi  = (const float*)d_in[8];
    const float* w_ctx  = (const float*)d_in[9];
    const float* w_self = (const float*)d_in[10];
    const float* b_self = (const float*)d_in[11];
    const float* w_out  = (const float*)d_in[12];
    const float* b_out  = (const float*)d_in[13];
    float* out = (float*)d_out;

    k_setup<<<1, 1024>>>(batch, q, w_phi, b_phi, w_ctx, out + OFF_MASK);
    k_proj<<<dim3(PROJC/64, TOTAL/64), 256>>>(x, w_attn, b_attn);
    k_xhat<<<(TOTAL*NF)/256, 256>>>(x, w_node, b_node, out + OFF_XHAT);
    k_z<<<dim3(NMAX/32, NE, BATCHES), 256>>>();
    k_rows<<<(BATCHES*NE*NMAX)/8, 256>>>();
    k_main<<<BATCHES*NE*NMAX, 128>>>(w_self, b_self, w_out, b_out, out + OFF_EHAT);
    k_edge<<<(BATCHES*NMAX*NMAX)/256, 256>>>(out + OFF_EDGE);
}

// round 2
// speedup vs baseline: 1.3919x; 1.3919x over previous
#include <cuda_runtime.h>
#include <math.h>

#define BATCHES 8
#define NMAX    128
#define PE      64
#define NE      5
#define DS      64
#define NF      8
#define TOTAL   (BATCHES*NMAX)       // 1024
#define PROJC   (4*NE*PE)            // 1280
#define ZCOUNT  (BATCHES*NE*NMAX*NMAX)
#define TABN    2048                 // gelu table entries over [-8,8], h = 1/128

#define OFF_EHAT 0
#define OFF_XHAT (BATCHES*NMAX*NMAX*NE)            // 655360
#define OFF_EDGE (OFF_XHAT + TOTAL*NF)             // 663552
#define OFF_MASK (OFF_EDGE + BATCHES*NMAX*NMAX)    // 794624

__device__ float  g_proj[TOTAL*PROJC];
__device__ float  g_z[ZCOUNT];
__device__ float  g_a[BATCHES*NE*NMAX];
__device__ float  g_r[BATCHES*NMAX];
__device__ int    g_node[BATCHES*NMAX];
__device__ int    g_mask[BATCHES*NMAX];
__device__ int    g_cnt[BATCHES];
__device__ float  g_coef[BATCHES];
__device__ float  g_u[DS];
__device__ float  g_v[DS];
__device__ float2 g_tab[TABN];

#define FMA2(d,a,b,c) asm("fma.rn.f32x2 %0, %1, %2, %3;" : "=l"(d) : "l"(a), "l"(b), "l"(c))

__device__ __forceinline__ unsigned long long dup2(float v) {
    unsigned int u = __float_as_uint(v);
    return (unsigned long long)u | ((unsigned long long)u << 32);
}
__device__ __forceinline__ float lo2(unsigned long long v) { return __uint_as_float((unsigned int)v); }
__device__ __forceinline__ float hi2(unsigned long long v) { return __uint_as_float((unsigned int)(v >> 32)); }

// ---------------------------------------------------------------------------
// K0: dense map, counts, coef, u/v, mask output, and the exact-gelu table.
// ---------------------------------------------------------------------------
__global__ void k_setup(const int* __restrict__ batch, const float* __restrict__ q,
                        const float* __restrict__ w_phi, const float* __restrict__ b_phi,
                        const float* __restrict__ w_ctx, float* __restrict__ out_mask) {
    __shared__ int s_start[BATCHES];
    __shared__ int s_cnt[BATCHES];
    __shared__ float s_v[TABN + 1];
    int t = threadIdx.x;                // 0..1023, one block
    if (t < BATCHES) { s_cnt[t] = 0; s_start[t] = 0; }
    g_node[t] = -1;
    g_mask[t] = 0;
    out_mask[t] = 0.0f;
    // gelu table nodes: x_i = -8 + i/128, exact erff
    for (int i = t; i <= TABN; i += 1024) {
        float xv = -8.0f + (float)i * (1.0f/128.0f);
        s_v[i] = 0.5f * xv * (1.0f + erff(xv * 0.7071067811865476f));
    }
    __syncthreads();
    int b = batch[t];
    if (t == 0 || batch[t-1] != b) s_start[b] = t;
    atomicAdd(&s_cnt[b], 1);
    __syncthreads();
    int pos = t - s_start[b];
    int di = b*NMAX + pos;
    g_node[di] = t;
    g_mask[di] = 1;
    out_mask[di] = 1.0f;
    for (int i = t; i < TABN; i += 1024)
        g_tab[i] = make_float2(s_v[i], s_v[i+1] - s_v[i]);
    if (t < BATCHES) {
        g_cnt[t] = s_cnt[t];
        float qq = q[t];
        float c = cosf(6.283185307179586f*qq);
        float s = sinf(6.283185307179586f*qq);
        g_coef[t] = (2.0f - c) / s;
    }
    if (t < DS) {
        float u = 0.f, v = 0.f;
        #pragma unroll 8
        for (int k = 0; k < DS; k++) {
            float wc = w_ctx[k*DS + t];
            u = fmaf(w_phi[k], wc, u);
            v = fmaf(b_phi[k], wc, v);
        }
        g_u[t] = u; g_v[t] = v;
    }
}

// ---------------------------------------------------------------------------
// K1: proj = x @ w_attn + b_attn (dense layout) AND x_hat (blockIdx.x == 20).
// ---------------------------------------------------------------------------
__global__ void k_projx(const float* __restrict__ x, const float* __restrict__ w,
                        const float* __restrict__ bias,
                        const float* __restrict__ w_node, const float* __restrict__ b_node,
                        float* __restrict__ out_xhat) {
    if (blockIdx.x == 20) {
        // x_hat slice: nodes [64*blockIdx.y, +64), 512 outputs, 256 threads
        int base = blockIdx.y * 512;
        #pragma unroll
        for (int l = 0; l < 2; l++) {
            int id = base + threadIdx.x + l*256;
            int node = id / NF, f = id % NF;
            float acc = 0.f;
            #pragma unroll 8
            for (int k = 0; k < PE; k++)
                acc = fmaf(__ldg(&x[node*PE + k]), __ldg(&w_node[k*NF + f]), acc);
            out_xhat[id] = acc + b_node[f];
        }
        return;
    }
    __shared__ float As[64][65];
    __shared__ float Ws[64][65];
    int tid = threadIdx.x;              // 256 threads
    int tx = tid & 15, ty = tid >> 4;   // 16x16
    int row0 = blockIdx.y * 64;
    int col0 = blockIdx.x * 64;
    #pragma unroll
    for (int l = 0; l < 16; l++) {
        int e = tid + l*256;
        int r = e >> 6, k = e & 63;
        int node = g_node[row0 + r];
        As[r][k] = (node >= 0) ? x[node*PE + k] : 0.0f;
    }
    #pragma unroll
    for (int l = 0; l < 16; l++) {
        int e = tid + l*256;
        int k = e >> 6, c = e & 63;
        Ws[k][c] = w[k*PROJC + col0 + c];
    }
    __syncthreads();
    float acc[4][4] = {};
    #pragma unroll 8
    for (int k = 0; k < 64; k++) {
        float a[4], bv[4];
        #pragma unroll
        for (int i = 0; i < 4; i++) a[i] = As[ty + i*16][k];
        #pragma unroll
        for (int j = 0; j < 4; j++) bv[j] = Ws[k][tx + j*16];
        #pragma unroll
        for (int i = 0; i < 4; i++)
            #pragma unroll
            for (int j = 0; j < 4; j++)
                acc[i][j] = fmaf(a[i], bv[j], acc[i][j]);
    }
    #pragma unroll
    for (int i = 0; i < 4; i++) {
        int r = row0 + ty + i*16;
        int node = g_node[r];
        #pragma unroll
        for (int j = 0; j < 4; j++) {
            int c = col0 + tx + j*16;
            g_proj[r*PROJC + c] = (node >= 0) ? (acc[i][j] + bias[c]) : 0.0f;
        }
    }
}

// ---------------------------------------------------------------------------
// K2: fused z GEMM (packed f32x2) + masked row means.
// z[b,e,n,m] = scale*(k1_n.q1_m + coef_b*(k2_n.q2_m))
// grid (8 tiles, NE, B), block 128. Tile = 16 rows x 128 cols.
// Warp wy owns rows wy*4+i (full rows) -> shfl row-sum -> g_a, g_r.
// ---------------------------------------------------------------------------
__global__ void k_zrows() {
    __shared__ unsigned long long Kd[64][17];   // duplicated K values [k][row]
    __shared__ float Qt[64][130];               // transposed Q [k][m]
    __shared__ float s_maskf[NMAX];
    const float scale = 0.05590169943749474f;   // 1/sqrt(320)
    int tid = threadIdx.x;
    int tx = tid & 31, wy = tid >> 5;           // 32 lanes x 4 warps
    int tile = blockIdx.x, e = blockIdx.y, b = blockIdx.z;
    int row0 = tile * 16;
    int base_row = b * NMAX;
    float coef = g_coef[b];
    if (tid < NMAX) s_maskf[tid] = (float)g_mask[base_row + tid];

    unsigned long long acc[4][2];
    #pragma unroll
    for (int i = 0; i < 4; i++) { acc[i][0] = 0ull; acc[i][1] = 0ull; }

    #pragma unroll
    for (int p = 0; p < 2; p++) {
        float cs = p ? coef : 1.0f;
        int koff = (p ? 2*NE*PE : 0) + e*PE;
        int qoff = (p ? 3*NE*PE : NE*PE) + e*PE;
        if (p) __syncthreads();                 // protect smem reuse
        // K tile: 16 rows x 64 k = 256 float4
        #pragma unroll
        for (int l = 0; l < 2; l++) {
            int e4 = tid + l*128;
            int r = e4 >> 4;
            int kq = (e4 & 15) * 4;
            float4 v = *(const float4*)&g_proj[(base_row + row0 + r)*PROJC + koff + kq];
            Kd[kq+0][r] = dup2(v.x * cs);
            Kd[kq+1][r] = dup2(v.y * cs);
            Kd[kq+2][r] = dup2(v.z * cs);
            Kd[kq+3][r] = dup2(v.w * cs);
        }
        // Q tile: 128 rows x 64 k = 2048 float4, stored transposed
        #pragma unroll
        for (int l = 0; l < 16; l++) {
            int e4 = tid + l*128;
            int r = e4 >> 4;
            int kq = (e4 & 15) * 4;
            float4 v = *(const float4*)&g_proj[(base_row + r)*PROJC + qoff + kq];
            Qt[kq+0][r] = v.x;
            Qt[kq+1][r] = v.y;
            Qt[kq+2][r] = v.z;
            Qt[kq+3][r] = v.w;
        }
        __syncthreads();
        #pragma unroll 4
        for (int k = 0; k < 64; k++) {
            unsigned long long b0 = *(const unsigned long long*)&Qt[k][2*tx];
            unsigned long long b1 = *(const unsigned long long*)&Qt[k][64 + 2*tx];
            #pragma unroll
            for (int i = 0; i < 4; i++) {
                unsigned long long aa = Kd[k][wy*4 + i];
                FMA2(acc[i][0], aa, b0, acc[i][0]);
                FMA2(acc[i][1], aa, b1, acc[i][1]);
            }
        }
    }

    int cnt = g_cnt[b];
    #pragma unroll
    for (int i = 0; i < 4; i++) {
        int n = row0 + wy*4 + i;
        float z0 = lo2(acc[i][0]) * scale;
        float z1 = hi2(acc[i][0]) * scale;
        float z2 = lo2(acc[i][1]) * scale;
        float z3 = hi2(acc[i][1]) * scale;
        long zb = (long)((b*NE + e)*NMAX + n) * NMAX;
        int m0 = 2*tx, m2 = 64 + 2*tx;
        *(float2*)&g_z[zb + m0] = make_float2(z0, z1);
        *(float2*)&g_z[zb + m2] = make_float2(z2, z3);
        float s = z0 * (s_maskf[m0]   * (float)(m0   != n))
                + z1 * (s_maskf[m0+1] * (float)(m0+1 != n))
                + z2 * (s_maskf[m2]   * (float)(m2   != n))
                + z3 * (s_maskf[m2+1] * (float)(m2+1 != n));
        #pragma unroll
        for (int off = 16; off > 0; off >>= 1)
            s += __shfl_xor_sync(0xffffffffu, s, off);
        if (tx == 0) {
            int mn = g_mask[base_row + n];
            float cm1 = (float)(cnt - 1);
            float denom = fmaxf(cm1, 1.0f);
            g_a[(b*NE + e)*NMAX + n] = mn ? (s / denom) : 0.0f;
            if (e == 0) g_r[base_row + n] = mn ? (cm1 / denom) : 0.0f;
        }
    }
}

// ---------------------------------------------------------------------------
// K3: gelu-sum via shared table + edge_mask writes.
// Block = (b, e, group of 4 n), 512 threads (t = nl*128 + m).
// e[b,e,n,m] = sum_d wo[d]*gelu(z*ws[d] + base[n][d]) + b_out -> e_hat[b,m,n,e]
// ---------------------------------------------------------------------------
__global__ void k_main(const float* __restrict__ w_self, const float* __restrict__ b_self,
                       const float* __restrict__ w_out, const float* __restrict__ b_out,
                       float* __restrict__ out_e, float* __restrict__ out_edge) {
    __shared__ float2 s_tab[TABN];
    __shared__ float2 s_c[DS];          // (w_self, w_out)
    __shared__ float  s_base[4][DS];
    int t = threadIdx.x;
    int ng = blockIdx.x, e = blockIdx.y, b = blockIdx.z;
    int m = t & 127, nl = t >> 7;
    int n = ng*4 + nl;
    // load table (2048 float2 = 1024 float4, 512 threads -> 2 each)
    #pragma unroll
    for (int l = 0; l < 2; l++) {
        int i = t + l*512;
        ((float4*)s_tab)[i] = ((const float4*)g_tab)[i];
    }
    if (t < DS) s_c[t] = make_float2(w_self[t], w_out[t]);
    if (t >= 512-256) {                 // 256 threads fill s_base
        int tt = t - 256;
        int d = tt & 63, nn = tt >> 6;
        int blk = (b*NE + e)*NMAX + ng*4 + nn;
        float a = g_a[blk];
        float r = g_r[b*NMAX + ng*4 + nn];
        s_base[nn][d] = fmaf(a, g_u[d], fmaf(r, g_v[d], b_self[d]));
    }
    __syncthreads();
    int blk = (b*NE + e)*NMAX + n;
    float zv = g_z[(long)blk*NMAX + m];
    float acc = 0.f;
    #pragma unroll 8
    for (int d = 0; d < DS; d++) {
        float2 c = s_c[d];
        float xx = fmaf(zv, c.x, s_base[nl][d]);
        float f = fmaf(xx, 128.0f, 1024.0f);
        int i = (int)f;
        i = min(max(i, 0), TABN - 1);
        float fr = f - (float)i;
        float2 tv = s_tab[i];
        float g = fmaf(fr, tv.y, tv.x);
        acc = fmaf(g, c.y, acc);
    }
    out_e[((long)(b*NMAX + m)*NMAX + n)*NE + e] = acc + b_out[0];
    if (e == 0) {
        int v = g_mask[b*NMAX + n] & g_mask[b*NMAX + m] & (int)(n != m);
        out_edge[(b*NMAX + n)*NMAX + m] = (float)v;
    }
}

extern "C" void kernel_launch(void* const* d_in, const int* in_sizes, int n_in,
                              void* d_out, int out_size) {
    const float* x      = (const float*)d_in[0];
    const int*   batch  = (const int*)  d_in[1];
    const float* q      = (const float*)d_in[2];
    const float* w_attn = (const float*)d_in[3];
    const float* b_attn = (const float*)d_in[4];
    const float* w_node = (const float*)d_in[5];
    const float* b_node = (const float*)d_in[6];
    const float* w_phi  = (const float*)d_in[7];
    const float* b_phi  = (const float*)d_in[8];
    const float* w_ctx  = (const float*)d_in[9];
    const float* w_self = (const float*)d_in[10];
    const float* b_self = (const float*)d_in[11];
    const float* w_out  = (const float*)d_in[12];
    const float* b_out  = (const float*)d_in[13];
    float* out = (float*)d_out;

    k_setup<<<1, 1024>>>(batch, q, w_phi, b_phi, w_ctx, out + OFF_MASK);
    k_projx<<<dim3(21, 16), 256>>>(x, w_attn, b_attn, w_node, b_node, out + OFF_XHAT);
    k_zrows<<<dim3(8, NE, BATCHES), 128>>>();
    k_main<<<dim3(32, NE, BATCHES), 512>>>(w_self, b_self, w_out, b_out,
                                           out + OFF_EHAT, out + OFF_EDGE);
}

// round 3
// speedup vs baseline: 1.4884x; 1.0694x over previous
#include <cuda_runtime.h>
#include <math.h>

#define BATCHES 8
#define NMAX    128
#define PE      64
#define NE      5
#define DS      64
#define NF      8
#define TOTAL   (BATCHES*NMAX)       // 1024
#define PROJC   (4*NE*PE)            // 1280
#define ZCOUNT  (BATCHES*NE*NMAX*NMAX)

#define OFF_EHAT 0
#define OFF_XHAT (BATCHES*NMAX*NMAX*NE)            // 655360
#define OFF_EDGE (OFF_XHAT + TOTAL*NF)             // 663552
#define OFF_MASK (OFF_EDGE + BATCHES*NMAX*NMAX)    // 794624

__device__ float  g_proj[TOTAL*PROJC];
__device__ float  g_z[ZCOUNT];
__device__ float  g_a[BATCHES*NE*NMAX];
__device__ float  g_r[BATCHES*NMAX];
__device__ int    g_node[BATCHES*NMAX];
__device__ int    g_mask[BATCHES*NMAX];
__device__ int    g_cnt[BATCHES];
__device__ float  g_coef[BATCHES];
__device__ float  g_u[DS];
__device__ float  g_v[DS];
__device__ float  g_sc[4];           // H1, HW0, HWU, HWV (all pre-halved)

#define FMA2(d,a,b,c) asm("fma.rn.f32x2 %0, %1, %2, %3;" : "=l"(d) : "l"(a), "l"(b), "l"(c))
#define MUL2(d,a,b)   asm("mul.rn.f32x2 %0, %1, %2;" : "=l"(d) : "l"(a), "l"(b))
#define PACK2(d,lo,hi) asm("mov.b64 %0, {%1, %2};" : "=l"(d) : "r"(__float_as_uint(lo)), "r"(__float_as_uint(hi)))

__device__ __forceinline__ unsigned long long dup2(float v) {
    unsigned long long d; PACK2(d, v, v); return d;
}
__device__ __forceinline__ float lo2(unsigned long long v) { return __uint_as_float((unsigned int)v); }
__device__ __forceinline__ float hi2(unsigned long long v) { return __uint_as_float((unsigned int)(v >> 32)); }

// Taylor coefficients of erf(x/sqrt(2)) = x * sum c_k x^(2k), valid |x|<=1.5 (err<4.5e-6)
#define C0  0.7978845608028654f
#define C1 (-0.13298076013381092f)
#define C2  0.019947114020071635f
#define C3 (-0.0023746564309608790f)
#define C4  2.3087512708529163e-4f
#define C5 (-1.8888357703977833e-5f)
#define C6  1.3319387846161196e-6f
#define C7 (-8.2452514340561257e-8f)

// ---------------------------------------------------------------------------
// K0: dense map, counts, coef, u/v, hoisted scalars, mask output.
// ---------------------------------------------------------------------------
__global__ void k_setup(const int* __restrict__ batch, const float* __restrict__ q,
                        const float* __restrict__ w_phi, const float* __restrict__ b_phi,
                        const float* __restrict__ w_ctx,
                        const float* __restrict__ w_self, const float* __restrict__ b_self,
                        const float* __restrict__ w_out,
                        float* __restrict__ out_mask) {
    __shared__ int s_start[BATCHES];
    __shared__ int s_cnt[BATCHES];
    __shared__ float s_red[4][64];
    int t = threadIdx.x;                // 0..1023, one block
    if (t < BATCHES) { s_cnt[t] = 0; s_start[t] = 0; }
    g_node[t] = -1;
    g_mask[t] = 0;
    out_mask[t] = 0.0f;
    __syncthreads();
    int b = batch[t];
    if (t == 0 || batch[t-1] != b) s_start[b] = t;
    atomicAdd(&s_cnt[b], 1);
    if (t < DS) {
        float u = 0.f, v = 0.f;
        #pragma unroll 8
        for (int k = 0; k < DS; k++) {
            float wc = w_ctx[k*DS + t];
            u = fmaf(w_phi[k], wc, u);
            v = fmaf(b_phi[k], wc, v);
        }
        g_u[t] = u; g_v[t] = v;
        float wo = w_out[t];
        s_red[0][t] = wo * w_self[t];
        s_red[1][t] = wo * b_self[t];
        s_red[2][t] = wo * u;
        s_red[3][t] = wo * v;
    }
    __syncthreads();
    int pos = t - s_start[b];
    int di = b*NMAX + pos;
    g_node[di] = t;
    g_mask[di] = 1;
    out_mask[di] = 1.0f;
    if (t < BATCHES) {
        g_cnt[t] = s_cnt[t];
        float qq = q[t];
        float c = cosf(6.283185307179586f*qq);
        float s = sinf(6.283185307179586f*qq);
        g_coef[t] = (2.0f - c) / s;
    }
    if (t < 32) {
        #pragma unroll
        for (int j = 0; j < 4; j++) {
            float sv = s_red[j][t] + s_red[j][t+32];
            #pragma unroll
            for (int off = 16; off > 0; off >>= 1)
                sv += __shfl_xor_sync(0xffffffffu, sv, off);
            if (t == 0) g_sc[j] = 0.5f * sv;
        }
    }
}

// ---------------------------------------------------------------------------
// K1: proj = x @ w_attn + b_attn (dense layout, packed f32x2)
//     AND x_hat (blockIdx.x == 20).
// ---------------------------------------------------------------------------
__global__ void k_projx(const float* __restrict__ x, const float* __restrict__ w,
                        const float* __restrict__ bias,
                        const float* __restrict__ w_node, const float* __restrict__ b_node,
                        float* __restrict__ out_xhat) {
    if (blockIdx.x == 20) {
        int base = blockIdx.y * 512;
        #pragma unroll
        for (int l = 0; l < 2; l++) {
            int id = base + threadIdx.x + l*256;
            int node = id / NF, f = id % NF;
            float acc = 0.f;
            #pragma unroll 8
            for (int k = 0; k < PE; k++)
                acc = fmaf(__ldg(&x[node*PE + k]), __ldg(&w_node[k*NF + f]), acc);
            out_xhat[id] = acc + b_node[f];
        }
        return;
    }
    __shared__ unsigned long long Ad[64][64];   // duplicated A, [row][k]   32KB
    __shared__ unsigned long long Wp[64][32];   // col-paired W, [k][pair]  16KB
    int tid = threadIdx.x;              // 256 threads
    int tx = tid & 15, ty = tid >> 4;   // 16x16
    int row0 = blockIdx.y * 64;
    int col0 = blockIdx.x * 64;
    #pragma unroll
    for (int l = 0; l < 4; l++) {
        int e = tid + l*256;            // 0..1023 (r, kq)
        int r = e >> 4, kq = (e & 15) * 4;
        int node = g_node[row0 + r];
        float4 v = make_float4(0.f,0.f,0.f,0.f);
        if (node >= 0) v = *(const float4*)&x[node*PE + kq];
        Ad[r][kq+0] = dup2(v.x);
        Ad[r][kq+1] = dup2(v.y);
        Ad[r][kq+2] = dup2(v.z);
        Ad[r][kq+3] = dup2(v.w);
    }
    #pragma unroll
    for (int l = 0; l < 4; l++) {
        int e = tid + l*256;            // (k, cq)
        int k = e >> 4, cq = (e & 15) * 4;
        float4 v = *(const float4*)&w[k*PROJC + col0 + cq];
        unsigned long long p0, p1;
        PACK2(p0, v.x, v.y);
        PACK2(p1, v.z, v.w);
        Wp[k][cq/2]   = p0;
        Wp[k][cq/2+1] = p1;
    }
    __syncthreads();
    unsigned long long acc[4][2];
    #pragma unroll
    for (int i = 0; i < 4; i++) { acc[i][0] = 0ull; acc[i][1] = 0ull; }
    #pragma unroll 4
    for (int kk = 0; kk < 64; kk += 2) {
        ulonglong2 ai[4];
        #pragma unroll
        for (int i = 0; i < 4; i++)
            ai[i] = *(const ulonglong2*)&Ad[ty + 16*i][kk];
        unsigned long long b00 = Wp[kk][tx],   b10 = Wp[kk][tx+16];
        unsigned long long b01 = Wp[kk+1][tx], b11 = Wp[kk+1][tx+16];
        #pragma unroll
        for (int i = 0; i < 4; i++) {
            FMA2(acc[i][0], ai[i].x, b00, acc[i][0]);
            FMA2(acc[i][0], ai[i].y, b01, acc[i][0]);
            FMA2(acc[i][1], ai[i].x, b10, acc[i][1]);
            FMA2(acc[i][1], ai[i].y, b11, acc[i][1]);
        }
    }
    #pragma unroll
    for (int i = 0; i < 4; i++) {
        int r = row0 + ty + 16*i;
        int node = g_node[r];
        #pragma unroll
        for (int j = 0; j < 2; j++) {
            int cp = tx + 16*j;
            int c = col0 + 2*cp;
            float v0 = 0.f, v1 = 0.f;
            if (node >= 0) {
                v0 = lo2(acc[i][j]) + bias[c];
                v1 = hi2(acc[i][j]) + bias[c+1];
            }
            *(float2*)&g_proj[r*PROJC + c] = make_float2(v0, v1);
        }
    }
}

// ---------------------------------------------------------------------------
// K2: fused z GEMM (packed f32x2) + masked row means.
// ---------------------------------------------------------------------------
__global__ void k_zrows() {
    __shared__ unsigned long long Kd[64][17];   // duplicated K values [k][row]
    __shared__ float Qt[64][130];               // transposed Q [k][m]
    __shared__ float s_maskf[NMAX];
    const float scale = 0.05590169943749474f;   // 1/sqrt(320)
    int tid = threadIdx.x;
    int tx = tid & 31, wy = tid >> 5;           // 32 lanes x 4 warps
    int tile = blockIdx.x, e = blockIdx.y, b = blockIdx.z;
    int row0 = tile * 16;
    int base_row = b * NMAX;
    float coef = g_coef[b];
    if (tid < NMAX) s_maskf[tid] = (float)g_mask[base_row + tid];

    unsigned long long acc[4][2];
    #pragma unroll
    for (int i = 0; i < 4; i++) { acc[i][0] = 0ull; acc[i][1] = 0ull; }

    #pragma unroll
    for (int p = 0; p < 2; p++) {
        float cs = p ? coef : 1.0f;
        int koff = (p ? 2*NE*PE : 0) + e*PE;
        int qoff = (p ? 3*NE*PE : NE*PE) + e*PE;
        if (p) __syncthreads();
        #pragma unroll
        for (int l = 0; l < 2; l++) {
            int e4 = tid + l*128;
            int r = e4 >> 4;
            int kq = (e4 & 15) * 4;
            float4 v = *(const float4*)&g_proj[(base_row + row0 + r)*PROJC + koff + kq];
            Kd[kq+0][r] = dup2(v.x * cs);
            Kd[kq+1][r] = dup2(v.y * cs);
            Kd[kq+2][r] = dup2(v.z * cs);
            Kd[kq+3][r] = dup2(v.w * cs);
        }
        #pragma unroll
        for (int l = 0; l < 16; l++) {
            int e4 = tid + l*128;
            int r = e4 >> 4;
            int kq = (e4 & 15) * 4;
            float4 v = *(const float4*)&g_proj[(base_row + r)*PROJC + qoff + kq];
            Qt[kq+0][r] = v.x;
            Qt[kq+1][r] = v.y;
            Qt[kq+2][r] = v.z;
            Qt[kq+3][r] = v.w;
        }
        __syncthreads();
        #pragma unroll 4
        for (int k = 0; k < 64; k++) {
            unsigned long long b0 = *(const unsigned long long*)&Qt[k][2*tx];
            unsigned long long b1 = *(const unsigned long long*)&Qt[k][64 + 2*tx];
            #pragma unroll
            for (int i = 0; i < 4; i++) {
                unsigned long long aa = Kd[k][wy*4 + i];
                FMA2(acc[i][0], aa, b0, acc[i][0]);
                FMA2(acc[i][1], aa, b1, acc[i][1]);
            }
        }
    }

    int cnt = g_cnt[b];
    #pragma unroll
    for (int i = 0; i < 4; i++) {
        int n = row0 + wy*4 + i;
        float z0 = lo2(acc[i][0]) * scale;
        float z1 = hi2(acc[i][0]) * scale;
        float z2 = lo2(acc[i][1]) * scale;
        float z3 = hi2(acc[i][1]) * scale;
        long zb = (long)((b*NE + e)*NMAX + n) * NMAX;
        int m0 = 2*tx, m2 = 64 + 2*tx;
        *(float2*)&g_z[zb + m0] = make_float2(z0, z1);
        *(float2*)&g_z[zb + m2] = make_float2(z2, z3);
        float s = z0 * (s_maskf[m0]   * (float)(m0   != n))
                + z1 * (s_maskf[m0+1] * (float)(m0+1 != n))
                + z2 * (s_maskf[m2]   * (float)(m2   != n))
                + z3 * (s_maskf[m2+1] * (float)(m2+1 != n));
        #pragma unroll
        for (int off = 16; off > 0; off >>= 1)
            s += __shfl_xor_sync(0xffffffffu, s, off);
        if (tx == 0) {
            int mn = g_mask[base_row + n];
            float cm1 = (float)(cnt - 1);
            float denom = fmaxf(cm1, 1.0f);
            g_a[(b*NE + e)*NMAX + n] = mn ? (s / denom) : 0.0f;
            if (e == 0) g_r[base_row + n] = mn ? (cm1 / denom) : 0.0f;
        }
    }
}

// ---------------------------------------------------------------------------
// K3: packed-polynomial gelu sum + edge_mask.
// Block = (ngroup of 4 n, e, b), 256 threads: t = nl*64 + mp; m = 2mp, 2mp+1.
// acc = sum_d wo2[d] * xx * erf(xx/sqrt2)  (poly in t=xx^2, f32x2 packed)
// e = acc + zv*H1 + S0[nl] + b_out
// ---------------------------------------------------------------------------
__global__ void k_main(const float* __restrict__ w_self, const float* __restrict__ b_self,
                       const float* __restrict__ w_out, const float* __restrict__ b_out,
                       float* __restrict__ out_e, float* __restrict__ out_edge) {
    __shared__ ulonglong2 s_A[4][DS];           // {ws_dup, base_dup}
    __shared__ unsigned long long s_W[DS];      // wo2_dup
    __shared__ float s_S0[4];
    int t = threadIdx.x;
    int ng = blockIdx.x, e = blockIdx.y, b = blockIdx.z;
    int mp = t & 63, nl = t >> 6;
    int n = ng*4 + nl;
    {   // fill stage: one (nl, d) per thread
        int d = t & 63, fl = t >> 6;
        int nn = ng*4 + fl;
        float a = g_a[(b*NE + e)*NMAX + nn];
        float r = g_r[b*NMAX + nn];
        float base = fmaf(a, g_u[d], fmaf(r, g_v[d], b_self[d]));
        s_A[fl][d] = make_ulonglong2(dup2(w_self[d]), dup2(base));
        if (d == 0)
            s_S0[fl] = fmaf(a, g_sc[2], fmaf(r, g_sc[3], g_sc[1]));
        if (t < DS) s_W[t] = dup2(0.5f * w_out[t]);
    }
    __syncthreads();

    const unsigned long long k0 = dup2(C0), k1 = dup2(C1), k2 = dup2(C2), k3 = dup2(C3);
    const unsigned long long k4 = dup2(C4), k5 = dup2(C5), k6 = dup2(C6), k7 = dup2(C7);

    long zb = (long)((b*NE + e)*NMAX + n) * NMAX;
    float2 z2 = *(const float2*)&g_z[zb + 2*mp];
    unsigned long long zv2; PACK2(zv2, z2.x, z2.y);

    unsigned long long acc = 0ull;
    float tmax = 0.0f;
    #pragma unroll 8
    for (int d = 0; d < DS; d++) {
        ulonglong2 ab = s_A[nl][d];
        unsigned long long xx, tt, p, q;
        FMA2(xx, zv2, ab.x, ab.y);
        MUL2(tt, xx, xx);
        p = k7;
        FMA2(p, p, tt, k6);
        FMA2(p, p, tt, k5);
        FMA2(p, p, tt, k4);
        FMA2(p, p, tt, k3);
        FMA2(p, p, tt, k2);
        FMA2(p, p, tt, k1);
        FMA2(p, p, tt, k0);
        MUL2(q, tt, p);
        FMA2(acc, s_W[d], q, acc);
        tmax = fmaxf(tmax, lo2(tt));
        tmax = fmaxf(tmax, hi2(tt));
    }
    if (tmax > 2.25f) {                 // rare exact fallback (|xx| > 1.5 seen)
        float al = 0.f, ah = 0.f;
        for (int d = 0; d < DS; d++) {
            ulonglong2 ab = s_A[nl][d];
            float ws = lo2(ab.x), base = lo2(ab.y), w2 = lo2(s_W[d]);
            float xl = fmaf(z2.x, ws, base);
            float xh = fmaf(z2.y, ws, base);
            al = fmaf(w2, xl * erff(xl * 0.7071067811865476f), al);
            ah = fmaf(w2, xh * erff(xh * 0.7071067811865476f), ah);
        }
        PACK2(acc, al, ah);
    }
    float h1 = g_sc[0];
    float cst = s_S0[nl] + b_out[0];
    float e0 = fmaf(z2.x, h1, lo2(acc)) + cst;
    float e1 = fmaf(z2.y, h1, hi2(acc)) + cst;
    int m = 2*mp;
    out_e[((long)(b*NMAX + m  )*NMAX + n)*NE + e] = e0;
    out_e[((long)(b*NMAX + m+1)*NMAX + n)*NE + e] = e1;
    if (e == 0) {
        int mn = g_mask[b*NMAX + n];
        float v0 = (float)(mn & g_mask[b*NMAX + m]   & (int)(n != m));
        float v1 = (float)(mn & g_mask[b*NMAX + m+1] & (int)(n != m+1));
        *(float2*)&out_edge[(b*NMAX + n)*NMAX + m] = make_float2(v0, v1);
    }
}

extern "C" void kernel_launch(void* const* d_in, const int* in_sizes, int n_in,
                              void* d_out, int out_size) {
    const float* x      = (const float*)d_in[0];
    const int*   batch  = (const int*)  d_in[1];
    const float* q      = (const float*)d_in[2];
    const float* w_attn = (const float*)d_in[3];
    const float* b_attn = (const float*)d_in[4];
    const float* w_node = (const float*)d_in[5];
    const float* b_node = (const float*)d_in[6];
    const float* w_phi  = (const float*)d_in[7];
    const float* b_phi  = (const float*)d_in[8];
    const float* w_ctx  = (const float*)d_in[9];
    const float* w_self = (const float*)d_in[10];
    const float* b_self = (const float*)d_in[11];
    const float* w_out  = (const float*)d_in[12];
    const float* b_out  = (const float*)d_in[13];
    float* out = (float*)d_out;

    k_setup<<<1, 1024>>>(batch, q, w_phi, b_phi, w_ctx, w_self, b_self, w_out, out + OFF_MASK);
    k_projx<<<dim3(21, 16), 256>>>(x, w_attn, b_attn, w_node, b_node, out + OFF_XHAT);
    k_zrows<<<dim3(8, NE, BATCHES), 128>>>();
    k_main<<<dim3(32, NE, BATCHES), 256>>>(w_self, b_self, w_out, b_out,
                                           out + OFF_EHAT, out + OFF_EDGE);
}